// round 3
// baseline (speedup 1.0000x reference)
#include <cuda_runtime.h>
#include <math.h>
#include <stdint.h>

// Problem constants
#define BB   1024
#define DM   512
#define NH   8
#define HD   64
#define NN   81     // 9x9 tokens
#define OC   1536   // 3*DM

// 510 MB scratch for qkv projection result, layout [B][1536][81]
__device__ float g_qkv[(size_t)BB * OC * NN];

__device__ __forceinline__ uint32_t f2tf32(float f) {
    uint32_t r;
    asm("cvt.rna.tf32.f32 %0, %1;" : "=r"(r) : "f"(f));
    return r;
}

// ---------------------------------------------------------------------------
// Kernel 1: QKV projection GEMM on TF32 tensor cores.
//   qkv[b][o][n] = sum_c W[o][c] * x[b][c][n] + bias[o]
// Block tile: 128 o x 96 n (n>=81 zero-padded), K tile 32.
// 8 warps = 4 (M) x 2 (N); warp tile 32x48 = 2x6 frags of m16n8k8.
// Smem strides 136 / 104 (both = 8 mod 32) -> conflict-free fragment LDS.
// ---------------------------------------------------------------------------
#define MB  128
#define NB  96
#define KB  32
#define WSS 136   // Ws[k][o] row stride
#define XSS 104   // Xs[k][n] row stride

__global__ __launch_bounds__(256) void qkv_gemm_tf32(const float* __restrict__ x,
                                                     const float* __restrict__ w,
                                                     const float* __restrict__ bias) {
    const int b  = blockIdx.y;
    const int o0 = blockIdx.x * MB;

    __shared__ uint32_t Ws[KB * WSS];   // 17408 B
    __shared__ uint32_t Xs[KB * XSS];   // 13312 B

    const int tid  = threadIdx.x;
    const int warp = tid >> 5;
    const int lane = tid & 31;
    const int wm   = warp & 3;          // 0..3: M position (32 rows each)
    const int wn   = warp >> 2;         // 0..1: N position (48 cols each)
    const int g    = lane >> 2;         // groupID 0..7
    const int l4   = lane & 3;          // 0..3

    float acc[2][6][4];
#pragma unroll
    for (int i = 0; i < 2; i++)
#pragma unroll
        for (int j = 0; j < 6; j++)
#pragma unroll
            for (int r = 0; r < 4; r++) acc[i][j][r] = 0.0f;

    const float* xb = x + (size_t)b * DM * NN;

    for (int k0 = 0; k0 < DM; k0 += KB) {
        // ---- Load W tile 128 x 32 as float4 (coalesced over k), store [k][o]
#pragma unroll
        for (int i = 0; i < 4; i++) {
            int idx = tid + i * 256;          // 0..1023 float4 slots
            int o   = idx >> 3;               // 8 float4 per row
            int kq  = (idx & 7) << 2;         // k offset 0,4,...,28
            float4 wv = *reinterpret_cast<const float4*>(
                w + (size_t)(o0 + o) * DM + k0 + kq);
            Ws[(kq + 0) * WSS + o] = f2tf32(wv.x);
            Ws[(kq + 1) * WSS + o] = f2tf32(wv.y);
            Ws[(kq + 2) * WSS + o] = f2tf32(wv.z);
            Ws[(kq + 3) * WSS + o] = f2tf32(wv.w);
        }
        // ---- Load X tile 32 x 96 (coalesced over n), zero pad n>=81
#pragma unroll
        for (int i = 0; i < 12; i++) {
            int idx = tid + i * 256;          // 0..3071
            int k   = idx / NB;
            int n   = idx - k * NB;
            float v = (n < NN) ? xb[(size_t)(k0 + k) * NN + n] : 0.0f;
            Xs[k * XSS + n] = f2tf32(v);
        }
        __syncthreads();

#pragma unroll
        for (int kf = 0; kf < 4; kf++) {
            const int kb = kf * 8;
            // A fragments (2 m-frags)
            uint32_t a[2][4];
#pragma unroll
            for (int mi = 0; mi < 2; mi++) {
                int row = wm * 32 + mi * 16 + g;
                a[mi][0] = Ws[(kb + l4) * WSS + row];
                a[mi][1] = Ws[(kb + l4) * WSS + row + 8];
                a[mi][2] = Ws[(kb + l4 + 4) * WSS + row];
                a[mi][3] = Ws[(kb + l4 + 4) * WSS + row + 8];
            }
            // B fragments (6 n-frags)
            uint32_t bfr[6][2];
#pragma unroll
            for (int ni = 0; ni < 6; ni++) {
                int n = wn * 48 + ni * 8 + g;
                bfr[ni][0] = Xs[(kb + l4) * XSS + n];
                bfr[ni][1] = Xs[(kb + l4 + 4) * XSS + n];
            }
#pragma unroll
            for (int mi = 0; mi < 2; mi++)
#pragma unroll
                for (int ni = 0; ni < 6; ni++) {
                    asm volatile(
                        "mma.sync.aligned.m16n8k8.row.col.f32.tf32.tf32.f32 "
                        "{%0,%1,%2,%3}, {%4,%5,%6,%7}, {%8,%9}, {%0,%1,%2,%3};\n"
                        : "+f"(acc[mi][ni][0]), "+f"(acc[mi][ni][1]),
                          "+f"(acc[mi][ni][2]), "+f"(acc[mi][ni][3])
                        : "r"(a[mi][0]), "r"(a[mi][1]), "r"(a[mi][2]), "r"(a[mi][3]),
                          "r"(bfr[ni][0]), "r"(bfr[ni][1]));
                }
        }
        __syncthreads();
    }

    // ---- Epilogue: bias + store to g_qkv (fp32)
#pragma unroll
    for (int mi = 0; mi < 2; mi++) {
        const int row = o0 + wm * 32 + mi * 16 + g;
        const float bv0 = bias[row];
        const float bv1 = bias[row + 8];
        float* dst0 = g_qkv + ((size_t)b * OC + row) * NN;
        float* dst1 = g_qkv + ((size_t)b * OC + row + 8) * NN;
#pragma unroll
        for (int ni = 0; ni < 6; ni++) {
            const int n = wn * 48 + ni * 8 + 2 * l4;
            if (n < NN)     dst0[n]     = acc[mi][ni][0] + bv0;
            if (n + 1 < NN) dst0[n + 1] = acc[mi][ni][1] + bv0;
            if (n < NN)     dst1[n]     = acc[mi][ni][2] + bv1;
            if (n + 1 < NN) dst1[n + 1] = acc[mi][ni][3] + bv1;
        }
    }
}

// ---------------------------------------------------------------------------
// Kernel 2: attention per (b, h) — unchanged fp32 path.
// ---------------------------------------------------------------------------
#define QP 65
#define SP 83
__global__ __launch_bounds__(256) void attn_kernel(const float* __restrict__ rel_h,
                                                   const float* __restrict__ rel_w,
                                                   float* __restrict__ out) {
    extern __shared__ float sm[];
    float* Qs = sm;                    // [81][65]
    float* Ks = sm + NN * QP;          // [81][65], later reused as V
    float* S  = sm + 2 * NN * QP;      // [81][83]

    const int bh = blockIdx.x;
    const int b  = bh >> 3;
    const int h  = bh & 7;
    const int tid = threadIdx.x;

    const float* qkvb = g_qkv + (size_t)b * OC * NN;
    const float* Qg = qkvb + (size_t)(h * HD) * NN;
    const float* Kg = qkvb + (size_t)(DM + h * HD) * NN;
    const float* Vg = qkvb + (size_t)(2 * DM + h * HD) * NN;

    for (int idx = tid; idx < HD * NN; idx += 256) {
        int d = idx / NN;
        int n = idx % NN;
        Qs[n * QP + d] = Qg[d * NN + n];
        float rh = rel_h[(h * HD + d) * 9 + (n % 9)];
        float rw = rel_w[(h * HD + d) * 9 + (n / 9)];
        Ks[n * QP + d] = Kg[d * NN + n] + rh + rw;
    }
    __syncthreads();

    for (int idx = tid; idx < NN * NN; idx += 256) {
        int n = idx / NN;
        int m = idx % NN;
        const float* qp = Qs + n * QP;
        const float* kp = Ks + m * QP;
        float s = 0.0f;
#pragma unroll
        for (int d = 0; d < HD; d++) s += qp[d] * kp[d];
        S[n * SP + m] = s;
    }
    __syncthreads();

    for (int idx = tid; idx < HD * NN; idx += 256) {
        int d = idx / NN;
        int n = idx % NN;
        Ks[n * QP + d] = Vg[d * NN + n];
    }
    if (tid < NN) {
        float* row = S + tid * SP;
        float mx = row[0];
        for (int m = 1; m < NN; m++) mx = fmaxf(mx, row[m]);
        float sum = 0.0f;
        for (int m = 0; m < NN; m++) {
            float e = __expf(row[m] - mx);
            row[m] = e;
            sum += e;
        }
        float inv = 1.0f / sum;
        for (int m = 0; m < NN; m++) row[m] *= inv;
    }
    __syncthreads();

    for (int idx = tid; idx < HD * NN; idx += 256) {
        int d = idx / NN;
        int n = idx % NN;
        const float* pr = S + n * SP;
        float acc = 0.0f;
#pragma unroll
        for (int m = 0; m < NN; m++) acc += pr[m] * Ks[m * QP + d];
        out[((size_t)b * DM + h * HD + d) * NN + n] = acc;
    }
}

// ---------------------------------------------------------------------------
extern "C" void kernel_launch(void* const* d_in, const int* in_sizes, int n_in,
                              void* d_out, int out_size) {
    const float* x     = (const float*)d_in[0];
    const float* qkv_w = (const float*)d_in[1];
    const float* qkv_b = (const float*)d_in[2];
    const float* rel_h = (const float*)d_in[3];
    const float* rel_w = (const float*)d_in[4];
    float* out = (float*)d_out;

    static const int SMEM_ATTN = (2 * NN * QP + NN * SP) * sizeof(float);
    cudaFuncSetAttribute(attn_kernel, cudaFuncAttributeMaxDynamicSharedMemorySize, SMEM_ATTN);

    dim3 g1(OC / MB, BB);
    qkv_gemm_tf32<<<g1, 256>>>(x, qkv_w, qkv_b);
    attn_kernel<<<BB * NH, 256, SMEM_ATTN>>>(rel_h, rel_w, out);
}

// round 4
// speedup vs baseline: 2.1118x; 2.1118x over previous
#include <cuda_runtime.h>
#include <cuda_bf16.h>
#include <math.h>
#include <stdint.h>

// Problem constants
#define BB   1024
#define DM   512
#define NH   8
#define HD   64
#define NN   81     // 9x9 tokens
#define OC   1536   // 3*DM

// 510 MB scratch for qkv projection result, layout [B][1536][81]
__device__ float g_qkv[(size_t)BB * OC * NN];

// ---------------------------------------------------------------------------
// Kernel 1: QKV projection GEMM on bf16 tensor cores with 2-term split.
//   a = hi + lo (bf16 each);  a*b ≈ ah*bh + ah*bl + al*bh  (fp32 accum)
// Block tile: 128 o x 96 n (n>=81 zero-padded), K tile 32 (2 k16 steps).
// 8 warps = 4 (M) x 2 (N); warp tile 32x48 = 2x6 frags of m16n8k16.
// Smem words pack two consecutive-k bf16; strides 136/104 (≡8 mod 32)
// -> conflict-free fragment LDS.
// ---------------------------------------------------------------------------
#define MB   128
#define NB   96
#define KB   32
#define KB2  16    // KB/2 packed words in k
#define WSS2 136   // W plane row stride (words)
#define XSS2 104   // X plane row stride (words)

__device__ __forceinline__ uint32_t pack2(float a, float b) {
    __nv_bfloat162 t = __floats2bfloat162_rn(a, b);   // low half = a
    return *reinterpret_cast<uint32_t*>(&t);
}

__device__ __forceinline__ void split2(float v, float& hi, float& lo) {
    float h = __bfloat162float(__float2bfloat16_rn(v));
    hi = h;
    lo = v - h;
}

#define MMA_BF16(C, A, B)                                                     \
    asm volatile(                                                             \
        "mma.sync.aligned.m16n8k16.row.col.f32.bf16.bf16.f32 "                \
        "{%0,%1,%2,%3}, {%4,%5,%6,%7}, {%8,%9}, {%0,%1,%2,%3};\n"             \
        : "+f"((C)[0]), "+f"((C)[1]), "+f"((C)[2]), "+f"((C)[3])              \
        : "r"((A)[0]), "r"((A)[1]), "r"((A)[2]), "r"((A)[3]),                 \
          "r"((B)[0]), "r"((B)[1]))

__global__ __launch_bounds__(256) void qkv_gemm_bf16s(const float* __restrict__ x,
                                                      const float* __restrict__ w,
                                                      const float* __restrict__ bias) {
    const int b  = blockIdx.y;
    const int o0 = blockIdx.x * MB;

    __shared__ uint32_t Wh[KB2 * WSS2];   // 8704 B each
    __shared__ uint32_t Wl[KB2 * WSS2];
    __shared__ uint32_t Xh[KB2 * XSS2];   // 6656 B each
    __shared__ uint32_t Xl[KB2 * XSS2];

    const int tid  = threadIdx.x;
    const int warp = tid >> 5;
    const int lane = tid & 31;
    const int wm   = warp & 3;          // M position (32 rows each)
    const int wn   = warp >> 2;         // N position (48 cols each)
    const int g    = lane >> 2;         // groupID 0..7
    const int l4   = lane & 3;          // 0..3

    float acc[2][6][4];
#pragma unroll
    for (int i = 0; i < 2; i++)
#pragma unroll
        for (int j = 0; j < 6; j++)
#pragma unroll
            for (int r = 0; r < 4; r++) acc[i][j][r] = 0.0f;

    const float* xb = x + (size_t)b * DM * NN;

    for (int k0 = 0; k0 < DM; k0 += KB) {
        // ---- W tile: 128 o x 32 k, float4 loads over k, split+pack ----
#pragma unroll
        for (int i = 0; i < 4; i++) {
            int idx = tid + i * 256;          // 1024 float4 slots
            int o   = idx >> 3;
            int kq  = (idx & 7) << 2;         // k = kq..kq+3
            float4 wv = *reinterpret_cast<const float4*>(
                w + (size_t)(o0 + o) * DM + k0 + kq);
            float h0, l0, h1, l1, h2, l2, h3, l3;
            split2(wv.x, h0, l0); split2(wv.y, h1, l1);
            split2(wv.z, h2, l2); split2(wv.w, h3, l3);
            int k2 = kq >> 1;
            Wh[(k2 + 0) * WSS2 + o] = pack2(h0, h1);
            Wh[(k2 + 1) * WSS2 + o] = pack2(h2, h3);
            Wl[(k2 + 0) * WSS2 + o] = pack2(l0, l1);
            Wl[(k2 + 1) * WSS2 + o] = pack2(l2, l3);
        }
        // ---- X tile: 32 k x 96 n, coalesced over n, split+pack ----
#pragma unroll
        for (int i = 0; i < 6; i++) {
            int idx = tid + i * 256;          // 16 k2 x 96 n = 1536
            int k2  = idx / NB;
            int n   = idx - k2 * NB;
            float v0 = 0.0f, v1 = 0.0f;
            if (n < NN) {
                v0 = xb[(size_t)(k0 + 2 * k2) * NN + n];
                v1 = xb[(size_t)(k0 + 2 * k2 + 1) * NN + n];
            }
            float h0, l0, h1, l1;
            split2(v0, h0, l0); split2(v1, h1, l1);
            Xh[k2 * XSS2 + n] = pack2(h0, h1);
            Xl[k2 * XSS2 + n] = pack2(l0, l1);
        }
        __syncthreads();

#pragma unroll
        for (int ks = 0; ks < 2; ks++) {      // two m16n8k16 steps per K tile
            const int kb2 = ks * 8;
            // A fragments (hi & lo planes), 2 m-frags each
            uint32_t ah[2][4], al[2][4];
#pragma unroll
            for (int mi = 0; mi < 2; mi++) {
                const int row = wm * 32 + mi * 16 + g;
                const int r0 = (kb2 + l4) * WSS2 + row;
                const int r1 = (kb2 + l4 + 4) * WSS2 + row;
                ah[mi][0] = Wh[r0];     ah[mi][1] = Wh[r0 + 8];
                ah[mi][2] = Wh[r1];     ah[mi][3] = Wh[r1 + 8];
                al[mi][0] = Wl[r0];     al[mi][1] = Wl[r0 + 8];
                al[mi][2] = Wl[r1];     al[mi][3] = Wl[r1 + 8];
            }
#pragma unroll
            for (int ni = 0; ni < 6; ni++) {
                const int n = wn * 48 + ni * 8 + g;
                uint32_t bh[2], bl[2];
                bh[0] = Xh[(kb2 + l4) * XSS2 + n];
                bh[1] = Xh[(kb2 + l4 + 4) * XSS2 + n];
                bl[0] = Xl[(kb2 + l4) * XSS2 + n];
                bl[1] = Xl[(kb2 + l4 + 4) * XSS2 + n];
#pragma unroll
                for (int mi = 0; mi < 2; mi++) {
                    MMA_BF16(acc[mi][ni], ah[mi], bh);   // hi*hi
                    MMA_BF16(acc[mi][ni], ah[mi], bl);   // hi*lo
                    MMA_BF16(acc[mi][ni], al[mi], bh);   // lo*hi
                }
            }
        }
        __syncthreads();
    }

    // ---- Epilogue: bias + store to g_qkv (fp32) ----
#pragma unroll
    for (int mi = 0; mi < 2; mi++) {
        const int row = o0 + wm * 32 + mi * 16 + g;
        const float bv0 = bias[row];
        const float bv1 = bias[row + 8];
        float* dst0 = g_qkv + ((size_t)b * OC + row) * NN;
        float* dst1 = g_qkv + ((size_t)b * OC + row + 8) * NN;
#pragma unroll
        for (int ni = 0; ni < 6; ni++) {
            const int n = wn * 48 + ni * 8 + 2 * l4;
            if (n < NN)     dst0[n]     = acc[mi][ni][0] + bv0;
            if (n + 1 < NN) dst0[n + 1] = acc[mi][ni][1] + bv0;
            if (n < NN)     dst1[n]     = acc[mi][ni][2] + bv1;
            if (n + 1 < NN) dst1[n + 1] = acc[mi][ni][3] + bv1;
        }
    }
}

// ---------------------------------------------------------------------------
// Kernel 2: attention per (b, h) — fp32 path (small share of runtime).
// ---------------------------------------------------------------------------
#define QP 65
#define SP 83
__global__ __launch_bounds__(256) void attn_kernel(const float* __restrict__ rel_h,
                                                   const float* __restrict__ rel_w,
                                                   float* __restrict__ out) {
    extern __shared__ float sm[];
    float* Qs = sm;                    // [81][65]
    float* Ks = sm + NN * QP;          // [81][65], later reused as V
    float* S  = sm + 2 * NN * QP;      // [81][83]

    const int bh = blockIdx.x;
    const int b  = bh >> 3;
    const int h  = bh & 7;
    const int tid = threadIdx.x;

    const float* qkvb = g_qkv + (size_t)b * OC * NN;
    const float* Qg = qkvb + (size_t)(h * HD) * NN;
    const float* Kg = qkvb + (size_t)(DM + h * HD) * NN;
    const float* Vg = qkvb + (size_t)(2 * DM + h * HD) * NN;

    for (int idx = tid; idx < HD * NN; idx += 256) {
        int d = idx / NN;
        int n = idx % NN;
        Qs[n * QP + d] = Qg[d * NN + n];
        float rh = rel_h[(h * HD + d) * 9 + (n % 9)];
        float rw = rel_w[(h * HD + d) * 9 + (n / 9)];
        Ks[n * QP + d] = Kg[d * NN + n] + rh + rw;
    }
    __syncthreads();

    for (int idx = tid; idx < NN * NN; idx += 256) {
        int n = idx / NN;
        int m = idx % NN;
        const float* qp = Qs + n * QP;
        const float* kp = Ks + m * QP;
        float s = 0.0f;
#pragma unroll
        for (int d = 0; d < HD; d++) s += qp[d] * kp[d];
        S[n * SP + m] = s;
    }
    __syncthreads();

    for (int idx = tid; idx < HD * NN; idx += 256) {
        int d = idx / NN;
        int n = idx % NN;
        Ks[n * QP + d] = Vg[d * NN + n];
    }
    if (tid < NN) {
        float* row = S + tid * SP;
        float mx = row[0];
        for (int m = 1; m < NN; m++) mx = fmaxf(mx, row[m]);
        float sum = 0.0f;
        for (int m = 0; m < NN; m++) {
            float e = __expf(row[m] - mx);
            row[m] = e;
            sum += e;
        }
        float inv = 1.0f / sum;
        for (int m = 0; m < NN; m++) row[m] *= inv;
    }
    __syncthreads();

    for (int idx = tid; idx < HD * NN; idx += 256) {
        int d = idx / NN;
        int n = idx % NN;
        const float* pr = S + n * SP;
        float acc = 0.0f;
#pragma unroll
        for (int m = 0; m < NN; m++) acc += pr[m] * Ks[m * QP + d];
        out[((size_t)b * DM + h * HD + d) * NN + n] = acc;
    }
}

// ---------------------------------------------------------------------------
extern "C" void kernel_launch(void* const* d_in, const int* in_sizes, int n_in,
                              void* d_out, int out_size) {
    const float* x     = (const float*)d_in[0];
    const float* qkv_w = (const float*)d_in[1];
    const float* qkv_b = (const float*)d_in[2];
    const float* rel_h = (const float*)d_in[3];
    const float* rel_w = (const float*)d_in[4];
    float* out = (float*)d_out;

    static const int SMEM_ATTN = (2 * NN * QP + NN * SP) * sizeof(float);
    cudaFuncSetAttribute(attn_kernel, cudaFuncAttributeMaxDynamicSharedMemorySize, SMEM_ATTN);

    dim3 g1(OC / MB, BB);
    qkv_gemm_bf16s<<<g1, 256>>>(x, qkv_w, qkv_b);
    attn_kernel<<<BB * NH, 256, SMEM_ATTN>>>(rel_h, rel_w, out);
}

// round 6
// speedup vs baseline: 2.6817x; 1.2699x over previous
#include <cuda_runtime.h>
#include <cuda_bf16.h>
#include <math.h>
#include <stdint.h>

// Problem constants
#define BB   1024
#define DM   512
#define NH   8
#define HD   64
#define NN   81
#define OC   1536

// GEMM tiling
#define MT     128          // o rows per CTA
#define NT     96           // padded n (81 -> 96)
#define KT     32           // k per pipeline stage
#define NTILES (DM / KT)    // 16
#define NSTG   3

// smem geometry: rows of 64B data + 16B pad (ldmatrix conflict-free)
#define RSTRIDE 80
#define APL  (MT * RSTRIDE)          // 10240 per A plane
#define BPL  (NT * RSTRIDE)          // 7680 per B plane
#define ASTG (2 * APL)               // 20480
#define BSTG (2 * BPL)               // 15360
#define STG_BYTES (ASTG + BSTG)      // 35840
#define SMEM_GEMM (NSTG * STG_BYTES) // 107520

// Scratch
__device__ float         g_qkv[(size_t)BB * OC * NN];
__device__ __nv_bfloat16 g_wh[(size_t)OC * DM];
__device__ __nv_bfloat16 g_wl[(size_t)OC * DM];
__device__ __nv_bfloat16 g_xh[(size_t)BB * NT * DM];
__device__ __nv_bfloat16 g_xl[(size_t)BB * NT * DM];

__device__ __forceinline__ void split2(float v, float& hi, float& lo) {
    float h = __bfloat162float(__float2bfloat16_rn(v));
    hi = h;
    lo = v - h;
}

__device__ __forceinline__ uint32_t smem_u32(const void* p) {
    uint32_t a;
    asm("{ .reg .u64 t; cvta.to.shared.u64 t, %1; cvt.u32.u64 %0, t; }" : "=r"(a) : "l"(p));
    return a;
}

#define CP16(dst, src) \
    asm volatile("cp.async.cg.shared.global [%0], [%1], 16;" :: "r"(dst), "l"(src))
#define CP_COMMIT() asm volatile("cp.async.commit_group;" ::: "memory")
#define CP_WAIT(n)  asm volatile("cp.async.wait_group %0;" :: "n"(n) : "memory")

#define LDSM4(r0, r1, r2, r3, addr)                                           \
    asm volatile("ldmatrix.sync.aligned.m8n8.x4.shared.b16 {%0,%1,%2,%3}, [%4];" \
        : "=r"(r0), "=r"(r1), "=r"(r2), "=r"(r3) : "r"(addr))

#define MMA_BF16(C, A, B)                                                     \
    asm volatile(                                                             \
        "mma.sync.aligned.m16n8k16.row.col.f32.bf16.bf16.f32 "                \
        "{%0,%1,%2,%3}, {%4,%5,%6,%7}, {%8,%9}, {%0,%1,%2,%3};\n"             \
        : "+f"((C)[0]), "+f"((C)[1]), "+f"((C)[2]), "+f"((C)[3])              \
        : "r"((A)[0]), "r"((A)[1]), "r"((A)[2]), "r"((A)[3]),                 \
          "r"((B)[0]), "r"((B)[1]))

// ---------------------------------------------------------------------------
// Prep: split W into bf16 hi/lo planes, layout [o][c] (k contiguous)
// ---------------------------------------------------------------------------
__global__ void prep_w(const float* __restrict__ w) {
    int i = blockIdx.x * 256 + threadIdx.x;
    float hi, lo;
    split2(w[i], hi, lo);
    g_wh[i] = __float2bfloat16_rn(hi);
    g_wl[i] = __float2bfloat16_rn(lo);
}

// ---------------------------------------------------------------------------
// Prep: split + transpose X -> [b][n(96)][c(512)] bf16 hi/lo (n>=81 zeroed)
// ---------------------------------------------------------------------------
__global__ __launch_bounds__(256) void prep_x(const float* __restrict__ x) {
    __shared__ float ts[64][83];
    const int b  = blockIdx.x;
    const int c0 = blockIdx.y * 64;
    const int tid = threadIdx.x;

    const float* xb = x + ((size_t)b * DM + c0) * NN;
    for (int idx = tid; idx < 64 * NN; idx += 256) {
        int c = idx / NN;
        int n = idx - c * NN;
        ts[c][n] = xb[(size_t)c * NN + n];
    }
    __syncthreads();

    for (int idx = tid; idx < NT * 64; idx += 256) {
        int n = idx >> 6;
        int c = idx & 63;
        float v = (n < NN) ? ts[c][n] : 0.0f;
        float hi, lo;
        split2(v, hi, lo);
        size_t dst = ((size_t)b * NT + n) * DM + c0 + c;
        g_xh[dst] = __float2bfloat16_rn(hi);
        g_xl[dst] = __float2bfloat16_rn(lo);
    }
}

// ---------------------------------------------------------------------------
// Stage loader: cp.async 16B chunks into [Ah | Al | Bh | Bl] for one K tile
// ---------------------------------------------------------------------------
__device__ __forceinline__ void load_stage(uint32_t sb, int stage, int k0,
                                           int o0, int b, int tid) {
    const uint32_t base = sb + stage * STG_BYTES;
#pragma unroll
    for (int i = 0; i < 4; i++) {               // A: 1024 chunks
        int idx   = tid + i * 256;
        int plane = idx >> 9;
        int r     = idx & 511;
        int row   = r >> 2;
        int chv   = r & 3;
        const __nv_bfloat16* src =
            (plane ? g_wl : g_wh) + (size_t)(o0 + row) * DM + k0 + chv * 8;
        CP16(base + plane * APL + row * RSTRIDE + chv * 16, src);
    }
#pragma unroll
    for (int i = 0; i < 3; i++) {               // B: 768 chunks
        int idx   = tid + i * 256;
        int plane = idx >= 384;
        int r     = plane ? idx - 384 : idx;
        int row   = r >> 2;
        int chv   = r & 3;
        const __nv_bfloat16* src =
            (plane ? g_xl : g_xh) + ((size_t)b * NT + row) * DM + k0 + chv * 8;
        CP16(base + ASTG + plane * BPL + row * RSTRIDE + chv * 16, src);
    }
    CP_COMMIT();
}

// ---------------------------------------------------------------------------
// Kernel 1: QKV GEMM, bf16 3-term split, ldmatrix + cp.async 3-stage pipeline
// 8 warps = 4(M) x 2(N); warp tile 32 x 48.
// ---------------------------------------------------------------------------
__global__ __launch_bounds__(256) void qkv_gemm_mma(const float* __restrict__ bias) {
    extern __shared__ char smem[];
    const uint32_t sb = smem_u32(smem);
    const int tid  = threadIdx.x;
    const int o0   = blockIdx.x * MT;
    const int b    = blockIdx.y;
    const int warp = tid >> 5;
    const int lane = tid & 31;
    const int wm   = warp & 3;
    const int wn   = warp >> 2;
    const int g    = lane >> 2;
    const int l4   = lane & 3;

    // ldmatrix per-thread address offsets (bytes)
    const uint32_t aoff = ((lane & 7) + ((lane >> 3) & 1) * 8) * RSTRIDE + (lane >> 4) * 16;
    const uint32_t boff = ((lane & 7) + ((lane >> 4) & 1) * 8) * RSTRIDE + ((lane >> 3) & 1) * 16;

    float acc[2][6][4];
#pragma unroll
    for (int i = 0; i < 2; i++)
#pragma unroll
        for (int j = 0; j < 6; j++)
#pragma unroll
            for (int r = 0; r < 4; r++) acc[i][j][r] = 0.0f;

    // prologue: fill NSTG-1 stages
    load_stage(sb, 0, 0, o0, b, tid);
    load_stage(sb, 1, KT, o0, b, tid);

    for (int ch = 0; ch < NTILES; ch++) {
        if (ch + NSTG - 1 < NTILES) { CP_WAIT(1); } else { CP_WAIT(0); }
        __syncthreads();
        if (ch + NSTG - 1 < NTILES)
            load_stage(sb, (ch + NSTG - 1) % NSTG, (ch + NSTG - 1) * KT, o0, b, tid);

        const uint32_t st  = sb + (ch % NSTG) * STG_BYTES;
        const uint32_t sAh = st;
        const uint32_t sAl = st + APL;
        const uint32_t sBh = st + ASTG;
        const uint32_t sBl = sBh + BPL;

#pragma unroll
        for (int ks = 0; ks < 2; ks++) {
            uint32_t ah[2][4], al[2][4];
#pragma unroll
            for (int mi = 0; mi < 2; mi++) {
                uint32_t ra = (uint32_t)((wm * 32 + mi * 16) * RSTRIDE + ks * 32) + aoff;
                LDSM4(ah[mi][0], ah[mi][1], ah[mi][2], ah[mi][3], sAh + ra);
                LDSM4(al[mi][0], al[mi][1], al[mi][2], al[mi][3], sAl + ra);
            }
#pragma unroll
            for (int pr = 0; pr < 3; pr++) {
                uint32_t rb = (uint32_t)((wn * 48 + pr * 16) * RSTRIDE + ks * 32) + boff;
                uint32_t bh[4], bl[4];
                LDSM4(bh[0], bh[1], bh[2], bh[3], sBh + rb);
                LDSM4(bl[0], bl[1], bl[2], bl[3], sBl + rb);
#pragma unroll
                for (int sub = 0; sub < 2; sub++) {
                    uint32_t* bhp = bh + sub * 2;
                    uint32_t* blp = bl + sub * 2;
#pragma unroll
                    for (int mi = 0; mi < 2; mi++) {
                        float* C = acc[mi][pr * 2 + sub];
                        MMA_BF16(C, ah[mi], bhp);   // hi*hi
                        MMA_BF16(C, ah[mi], blp);   // hi*lo
                        MMA_BF16(C, al[mi], bhp);   // lo*hi
                    }
                }
            }
        }
    }

    // ---- Epilogue: bias + fp32 stores ----
#pragma unroll
    for (int mi = 0; mi < 2; mi++) {
        const int oa = o0 + wm * 32 + mi * 16 + g;
        const float bva = bias[oa];
        const float bvb = bias[oa + 8];
        float* da = g_qkv + ((size_t)b * OC + oa) * NN;
        float* db = da + (size_t)8 * NN;
#pragma unroll
        for (int f = 0; f < 6; f++) {
            const int n = wn * 48 + f * 8 + 2 * l4;
            if (n < NN)     { da[n]     = acc[mi][f][0] + bva;
                              db[n]     = acc[mi][f][2] + bvb; }
            if (n + 1 < NN) { da[n + 1] = acc[mi][f][1] + bva;
                              db[n + 1] = acc[mi][f][3] + bvb; }
        }
    }
}

// ---------------------------------------------------------------------------
// Kernel 2: attention per (b, h) — fp32.
// ---------------------------------------------------------------------------
#define QP 65
#define SP 83
__global__ __launch_bounds__(256) void attn_kernel(const float* __restrict__ rel_h,
                                                   const float* __restrict__ rel_w,
                                                   float* __restrict__ out) {
    extern __shared__ float sm[];
    float* Qs = sm;
    float* Ks = sm + NN * QP;
    float* S  = sm + 2 * NN * QP;

    const int bh = blockIdx.x;
    const int b  = bh >> 3;
    const int h  = bh & 7;
    const int tid = threadIdx.x;

    const float* qkvb = g_qkv + (size_t)b * OC * NN;
    const float* Qg = qkvb + (size_t)(h * HD) * NN;
    const float* Kg = qkvb + (size_t)(DM + h * HD) * NN;
    const float* Vg = qkvb + (size_t)(2 * DM + h * HD) * NN;

    for (int idx = tid; idx < HD * NN; idx += 256) {
        int d = idx / NN;
        int n = idx % NN;
        Qs[n * QP + d] = Qg[d * NN + n];
        float rh = rel_h[(h * HD + d) * 9 + (n % 9)];
        float rw = rel_w[(h * HD + d) * 9 + (n / 9)];
        Ks[n * QP + d] = Kg[d * NN + n] + rh + rw;
    }
    __syncthreads();

    for (int idx = tid; idx < NN * NN; idx += 256) {
        int n = idx / NN;
        int m = idx % NN;
        const float* qp = Qs + n * QP;
        const float* kp = Ks + m * QP;
        float s = 0.0f;
#pragma unroll
        for (int d = 0; d < HD; d++) s += qp[d] * kp[d];
        S[n * SP + m] = s;
    }
    __syncthreads();

    for (int idx = tid; idx < HD * NN; idx += 256) {
        int d = idx / NN;
        int n = idx % NN;
        Ks[n * QP + d] = Vg[d * NN + n];
    }
    if (tid < NN) {
        float* row = S + tid * SP;
        float mx = row[0];
        for (int m = 1; m < NN; m++) mx = fmaxf(mx, row[m]);
        float sum = 0.0f;
        for (int m = 0; m < NN; m++) {
            float e = __expf(row[m] - mx);
            row[m] = e;
            sum += e;
        }
        float inv = 1.0f / sum;
        for (int m = 0; m < NN; m++) row[m] *= inv;
    }
    __syncthreads();

    for (int idx = tid; idx < HD * NN; idx += 256) {
        int d = idx / NN;
        int n = idx % NN;
        const float* pr = S + n * SP;
        float acc = 0.0f;
#pragma unroll
        for (int m = 0; m < NN; m++) acc += pr[m] * Ks[m * QP + d];
        out[((size_t)b * DM + h * HD + d) * NN + n] = acc;
    }
}

// ---------------------------------------------------------------------------
extern "C" void kernel_launch(void* const* d_in, const int* in_sizes, int n_in,
                              void* d_out, int out_size) {
    const float* x     = (const float*)d_in[0];
    const float* qkv_w = (const float*)d_in[1];
    const float* qkv_b = (const float*)d_in[2];
    const float* rel_h = (const float*)d_in[3];
    const float* rel_w = (const float*)d_in[4];
    float* out = (float*)d_out;

    static const int SMEM_ATTN = (2 * NN * QP + NN * SP) * sizeof(float);
    cudaFuncSetAttribute(attn_kernel, cudaFuncAttributeMaxDynamicSharedMemorySize, SMEM_ATTN);
    cudaFuncSetAttribute(qkv_gemm_mma, cudaFuncAttributeMaxDynamicSharedMemorySize, SMEM_GEMM);

    prep_w<<<OC * DM / 256, 256>>>(qkv_w);
    prep_x<<<dim3(BB, DM / 64), 256>>>(x);
    qkv_gemm_mma<<<dim3(OC / MT, BB), 256, SMEM_GEMM>>>(qkv_b);
    attn_kernel<<<BB * NH, 256, SMEM_ATTN>>>(rel_h, rel_w, out);
}